// round 1
// baseline (speedup 1.0000x reference)
#include <cuda_runtime.h>

// SpatialTransformer: 1-D bilinear warp along W.
// out[b,c,h,w] = (1-oob) * (wa * in[b,c,h,ia] + wb * in[b,c,h,ib])
// where ry = w + disp[b,0,h,w]; ia = clip(floor(ry)); ib = clip(floor(ry)+1);
// wa = floor(ry)+1 - ry; wb = ry - floor(ry); oob = (ry<0) || (ry>W-1).
//
// Weights/indices are channel-invariant -> one thread per pixel (b,h,w),
// loop over C with stride H*W. All global accesses coalesced across w.

#ifndef ST_B
#define ST_B 4
#define ST_C 64
#define ST_H 256
#define ST_W 512
#endif

__global__ void __launch_bounds__(256)
spatial_transformer_kernel(const float* __restrict__ in,
                           const float* __restrict__ disp,
                           float* __restrict__ out)
{
    constexpr int C  = ST_C;
    constexpr int H  = ST_H;
    constexpr int W  = ST_W;
    constexpr int HW = H * W;
    constexpr int NPIX = ST_B * HW;

    int p = blockIdx.x * blockDim.x + threadIdx.x;   // pixel id in [0, B*H*W)
    if (p >= NPIX) return;

    int b   = p / HW;
    int rhw = p - b * HW;      // h*W + w
    int w   = rhw & (W - 1);   // W = 512 is a power of two

    float d  = __ldg(disp + p);
    float ry = (float)w + d;
    float ra = floorf(ry);
    float wb = ry - ra;
    float wa = 1.0f - wb;

    int ia = (int)ra;
    int ib = ia + 1;
    ia = min(max(ia, 0), W - 1);
    ib = min(max(ib, 0), W - 1);

    // zero the whole channel column if the unclamped coordinate is OOB
    float scale = (ry < 0.0f || ry > (float)(W - 1)) ? 0.0f : 1.0f;
    wa *= scale;
    wb *= scale;

    const float* src = in  + (long long)b * C * HW + (rhw - w); // row base, c=0
    float*       dst = out + (long long)b * C * HW + (rhw - w);

    #pragma unroll 4
    for (int c = 0; c < C; ++c) {
        float fa = __ldg(src + ia);
        float fb = __ldg(src + ib);
        dst[w] = fmaf(wa, fa, wb * fb);
        src += HW;
        dst += HW;
    }
}

extern "C" void kernel_launch(void* const* d_in, const int* in_sizes, int n_in,
                              void* d_out, int out_size)
{
    const float* right_input = (const float*)d_in[0];
    const float* disparity   = (const float*)d_in[1];
    float*       out         = (float*)d_out;

    constexpr int NPIX = ST_B * ST_H * ST_W;
    const int threads = 256;
    const int blocks  = (NPIX + threads - 1) / threads;
    spatial_transformer_kernel<<<blocks, threads>>>(right_input, disparity, out);
}